// round 9
// baseline (speedup 1.0000x reference)
#include <cuda_runtime.h>
#include <cuda_bf16.h>
#include <mma.h>
#include <cstdint>

using namespace nvcuda;

// Problem constants
#define Bb 4
#define Ss 128
#define Dd 768
#define Hh 768
#define MT (Bb * Ss)          // 512 rows per projection GEMM
#define NA (MT * Dd)          // 393216 elements in a (and in b)
#define NW (2 * Dd * Hh)      // 1179648 elements in W1

// ---------------------------------------------------------------------------
// Device scratch (allocation-free rule: __device__ globals)
// ---------------------------------------------------------------------------
__device__ float g_ha[MT * Hh];   // a @ W1[:D] + b1
__device__ float g_hb[MT * Hh];   // b @ W1[D:]

// bf16 split operands, SAME layout as sources
__device__ __align__(16) __nv_bfloat16 g_xa_hi[NA], g_xa_lo[NA];   // [m][d]
__device__ __align__(16) __nv_bfloat16 g_xb_hi[NA], g_xb_lo[NA];   // [m][d]
__device__ __align__(16) __nv_bfloat16 g_w_hi[NW],  g_w_lo[NW];    // [d'][h]

// pair-stage partial sums (2 h-halves)
__device__ __align__(16) float2 g_part[2][Bb * Ss * Ss];

// ---------------------------------------------------------------------------
// split_kernel: fused fp32 -> (hi, lo) bf16 split for a, b, W1.
// 8 elems/thread (2x float4) for MLP. 960 blocks x 256 thr.
// ---------------------------------------------------------------------------
__global__ __launch_bounds__(256) void split_kernel(
    const float* __restrict__ a, const float* __restrict__ b,
    const float* __restrict__ W1)
{
    int i8 = (blockIdx.x * 256 + threadIdx.x) * 8;
    const float* __restrict__ src;
    __nv_bfloat16 *dhi, *dlo;
    int off;
    if (i8 < NA)            { src = a;  dhi = g_xa_hi; dlo = g_xa_lo; off = i8; }
    else if (i8 < 2 * NA)   { src = b;  dhi = g_xb_hi; dlo = g_xb_lo; off = i8 - NA; }
    else                    { src = W1; dhi = g_w_hi;  dlo = g_w_lo;  off = i8 - 2 * NA; }

    float4 v0 = *reinterpret_cast<const float4*>(src + off);
    float4 v1 = *reinterpret_cast<const float4*>(src + off + 4);

    float f[8] = {v0.x, v0.y, v0.z, v0.w, v1.x, v1.y, v1.z, v1.w};
    __nv_bfloat16 h[8], l[8];
    #pragma unroll
    for (int i = 0; i < 8; i++) {
        h[i] = __float2bfloat16(f[i]);
        l[i] = __float2bfloat16(f[i] - __bfloat162float(h[i]));
    }
    *reinterpret_cast<uint4*>(dhi + off) = *reinterpret_cast<uint4*>(h);
    *reinterpret_cast<uint4*>(dlo + off) = *reinterpret_cast<uint4*>(l);
}

// ---------------------------------------------------------------------------
// gemm_kernel: h[z] = X[z] @ W1[z] (+ b1 for z=0), wmma bf16 HMMA — UNCHANGED
// from 51.7us round. 3 split terms: hi*Whi + lo*Whi + hi*Wlo.
// BM=128, BN=64, BK=32, 24 k-blocks, 8 warps (4x2), warp tile 32x32.
// grid (4, 12, 2) = 96 CTAs, 256 threads, dynamic smem 59.6KB.
// ---------------------------------------------------------------------------
#define GBM 128
#define GBN 64
#define GBK 32
#define LDA 40
#define LDB 72
#define LDC 68
#define NKB (Dd / GBK)   // 24

#define OFF_AH 0
#define OFF_AL (OFF_AH + 2 * GBM * LDA * 2)
#define OFF_BH (OFF_AL + 2 * GBM * LDA * 2)
#define OFF_BL (OFF_BH + 2 * GBK * LDB * 2)
#define OFF_END (OFF_BL + 2 * GBK * LDB * 2)
#define OFF_BIAS OFF_END
#define SM_TOT (OFF_BIAS + 256)

__global__ __launch_bounds__(256) void gemm_kernel(const float* __restrict__ b1)
{
    extern __shared__ __align__(16) char sm[];
    __nv_bfloat16 (*AsH)[GBM][LDA] = reinterpret_cast<__nv_bfloat16(*)[GBM][LDA]>(sm + OFF_AH);
    __nv_bfloat16 (*AsL)[GBM][LDA] = reinterpret_cast<__nv_bfloat16(*)[GBM][LDA]>(sm + OFF_AL);
    __nv_bfloat16 (*BsH)[GBK][LDB] = reinterpret_cast<__nv_bfloat16(*)[GBK][LDB]>(sm + OFF_BH);
    __nv_bfloat16 (*BsL)[GBK][LDB] = reinterpret_cast<__nv_bfloat16(*)[GBK][LDB]>(sm + OFF_BL);
    float (*Cs)[LDC] = reinterpret_cast<float(*)[LDC]>(sm);
    float* bias = reinterpret_cast<float*>(sm + OFF_BIAS);

    const int tid = threadIdx.x;
    const int wid = tid >> 5;
    const int wm = wid & 3;
    const int wn = wid >> 2;
    const int m_tile = blockIdx.x * GBM;
    const int n_tile = blockIdx.y * GBN;
    const int z = blockIdx.z;

    const __nv_bfloat16* __restrict__ XH = z ? g_xb_hi : g_xa_hi;
    const __nv_bfloat16* __restrict__ XL = z ? g_xb_lo : g_xa_lo;
    const __nv_bfloat16* __restrict__ WH = g_w_hi + (size_t)z * Dd * Hh;
    const __nv_bfloat16* __restrict__ WL = g_w_lo + (size_t)z * Dd * Hh;
    float* __restrict__ Cg = z ? g_hb : g_ha;

    if (tid < GBN)
        bias[tid] = z ? 0.f : b1[n_tile + tid];

    const int ar0 = tid >> 2;
    const int ar1 = (tid + 256) >> 2;
    const int ac  = (tid & 3) * 8;
    const int br = tid >> 3;
    const int bc = (tid & 7) * 8;

    const __nv_bfloat16* XHp0 = XH + (size_t)(m_tile + ar0) * Dd + ac;
    const __nv_bfloat16* XHp1 = XH + (size_t)(m_tile + ar1) * Dd + ac;
    const __nv_bfloat16* XLp0 = XL + (size_t)(m_tile + ar0) * Dd + ac;
    const __nv_bfloat16* XLp1 = XL + (size_t)(m_tile + ar1) * Dd + ac;
    const __nv_bfloat16* WHp  = WH + (size_t)br * Hh + n_tile + bc;
    const __nv_bfloat16* WLp  = WL + (size_t)br * Hh + n_tile + bc;

    {
        *reinterpret_cast<uint4*>(&AsH[0][ar0][ac]) = *reinterpret_cast<const uint4*>(XHp0);
        *reinterpret_cast<uint4*>(&AsH[0][ar1][ac]) = *reinterpret_cast<const uint4*>(XHp1);
        *reinterpret_cast<uint4*>(&AsL[0][ar0][ac]) = *reinterpret_cast<const uint4*>(XLp0);
        *reinterpret_cast<uint4*>(&AsL[0][ar1][ac]) = *reinterpret_cast<const uint4*>(XLp1);
        *reinterpret_cast<uint4*>(&BsH[0][br][bc])  = *reinterpret_cast<const uint4*>(WHp);
        *reinterpret_cast<uint4*>(&BsL[0][br][bc])  = *reinterpret_cast<const uint4*>(WLp);
    }
    __syncthreads();

    wmma::fragment<wmma::accumulator, 16, 16, 16, float> acc[2][2];
    #pragma unroll
    for (int i = 0; i < 2; i++)
        #pragma unroll
        for (int j = 0; j < 2; j++)
            wmma::fill_fragment(acc[i][j], 0.f);

    uint4 pah0, pah1, pal0, pal1, pbh, pbl;
    for (int kb = 0; kb < NKB; kb++) {
        const int cur = kb & 1;
        if (kb + 1 < NKB) {
            const int ko = (kb + 1) * GBK;
            pah0 = *reinterpret_cast<const uint4*>(XHp0 + ko);
            pah1 = *reinterpret_cast<const uint4*>(XHp1 + ko);
            pal0 = *reinterpret_cast<const uint4*>(XLp0 + ko);
            pal1 = *reinterpret_cast<const uint4*>(XLp1 + ko);
            pbh  = *reinterpret_cast<const uint4*>(WHp + (size_t)ko * Hh);
            pbl  = *reinterpret_cast<const uint4*>(WLp + (size_t)ko * Hh);
        }

        #pragma unroll
        for (int ks = 0; ks < GBK; ks += 16) {
            wmma::fragment<wmma::matrix_a, 16, 16, 16, __nv_bfloat16,
                           wmma::row_major> afH[2], afL[2];
            wmma::fragment<wmma::matrix_b, 16, 16, 16, __nv_bfloat16,
                           wmma::row_major> bfH[2], bfL[2];
            #pragma unroll
            for (int i = 0; i < 2; i++) {
                wmma::load_matrix_sync(afH[i], &AsH[cur][wm * 32 + 16 * i][ks], LDA);
                wmma::load_matrix_sync(afL[i], &AsL[cur][wm * 32 + 16 * i][ks], LDA);
            }
            #pragma unroll
            for (int j = 0; j < 2; j++) {
                wmma::load_matrix_sync(bfH[j], &BsH[cur][ks][wn * 32 + 16 * j], LDB);
                wmma::load_matrix_sync(bfL[j], &BsL[cur][ks][wn * 32 + 16 * j], LDB);
            }
            #pragma unroll
            for (int i = 0; i < 2; i++)
                #pragma unroll
                for (int j = 0; j < 2; j++) {
                    wmma::mma_sync(acc[i][j], afH[i], bfH[j], acc[i][j]);
                    wmma::mma_sync(acc[i][j], afL[i], bfH[j], acc[i][j]);
                    wmma::mma_sync(acc[i][j], afH[i], bfL[j], acc[i][j]);
                }
        }

        if (kb + 1 < NKB) {
            const int nxt = cur ^ 1;
            *reinterpret_cast<uint4*>(&AsH[nxt][ar0][ac]) = pah0;
            *reinterpret_cast<uint4*>(&AsH[nxt][ar1][ac]) = pah1;
            *reinterpret_cast<uint4*>(&AsL[nxt][ar0][ac]) = pal0;
            *reinterpret_cast<uint4*>(&AsL[nxt][ar1][ac]) = pal1;
            *reinterpret_cast<uint4*>(&BsH[nxt][br][bc])  = pbh;
            *reinterpret_cast<uint4*>(&BsL[nxt][br][bc])  = pbl;
        }
        __syncthreads();
    }

    #pragma unroll
    for (int i = 0; i < 2; i++)
        #pragma unroll
        for (int j = 0; j < 2; j++)
            wmma::store_matrix_sync(&Cs[wm * 32 + 16 * i][wn * 32 + 16 * j],
                                    acc[i][j], LDC, wmma::mem_row_major);
    __syncthreads();

    for (int t = tid; t < GBM * (GBN / 4); t += 256) {
        int r  = t >> 4;
        int c4 = (t & 15) * 4;
        float4 v = *reinterpret_cast<const float4*>(&Cs[r][c4]);
        v.x += bias[c4];
        v.y += bias[c4 + 1];
        v.z += bias[c4 + 2];
        v.w += bias[c4 + 3];
        *reinterpret_cast<float4*>(
            Cg + (size_t)(m_tile + r) * Hh + n_tile + c4) = v;
    }
}

// ---------------------------------------------------------------------------
// pair_kernel v2: partial[hh][b,i,j,:] = relu(ha+hb)[:, hh*384:(hh+1)*384] @ W2
// 2-way h-split across blockIdx.z (grid (8,4,8) = 256 CTAs, 2048 warps).
// Scalar-FFMA inner loop (no packing MOVs): per 4h per thread(2 pairs):
// 5 LDS.128 + 8 FADD + 8 FMNMX + 16 FFMA.
// ---------------------------------------------------------------------------
#define TI 16
#define TJ 32
#define HC 128
#define PP 132
#define HHALF 384

__global__ __launch_bounds__(256) void pair_kernel(const float* __restrict__ W2)
{
    __shared__ float sha[TI][PP];
    __shared__ float shb[TJ][PP];
    __shared__ float2 sw2[HC];     // (W2[h,0], W2[h,1]) for current chunk

    const int tid = threadIdx.x;
    const int bi = blockIdx.x, bj = blockIdx.y;
    const int bb = blockIdx.z >> 1;
    const int hh = blockIdx.z & 1;
    const int hbase = hh * HHALF;

    const int li = tid >> 4;   // 0..15 : i within tile
    const int lj = tid & 15;   // j and j+16 within tile

    const float* haBase = g_ha + (size_t)(bb * Ss + bi * TI) * Hh + hbase;
    const float* hbBase = g_hb + (size_t)(bb * Ss + bj * TJ) * Hh + hbase;
    const float* w2Base = W2 + 2 * hbase;

    // acc[j][o]
    float a00 = 0.f, a01 = 0.f, a10 = 0.f, a11 = 0.f;

    float4 va[2], vb[4], vw;
    {
        #pragma unroll
        for (int r = 0; r < 2; r++) {
            int idx = r * 256 + tid;
            va[r] = *reinterpret_cast<const float4*>(
                haBase + (size_t)(idx >> 5) * Hh + ((idx & 31) << 2));
        }
        #pragma unroll
        for (int r = 0; r < 4; r++) {
            int idx = r * 256 + tid;
            vb[r] = *reinterpret_cast<const float4*>(
                hbBase + (size_t)(idx >> 5) * Hh + ((idx & 31) << 2));
        }
        if (tid < 64) vw = *reinterpret_cast<const float4*>(w2Base + tid * 4);
    }

    for (int h0 = 0; h0 < HHALF; h0 += HC) {
        __syncthreads();
        #pragma unroll
        for (int r = 0; r < 2; r++) {
            int idx = r * 256 + tid;
            *reinterpret_cast<float4*>(&sha[idx >> 5][(idx & 31) << 2]) = va[r];
        }
        #pragma unroll
        for (int r = 0; r < 4; r++) {
            int idx = r * 256 + tid;
            *reinterpret_cast<float4*>(&shb[idx >> 5][(idx & 31) << 2]) = vb[r];
        }
        if (tid < 64) *reinterpret_cast<float4*>(&sw2[tid * 2]) = vw;
        __syncthreads();

        if (h0 + HC < HHALF) {
            int hn = h0 + HC;
            #pragma unroll
            for (int r = 0; r < 2; r++) {
                int idx = r * 256 + tid;
                va[r] = *reinterpret_cast<const float4*>(
                    haBase + (size_t)(idx >> 5) * Hh + hn + ((idx & 31) << 2));
            }
            #pragma unroll
            for (int r = 0; r < 4; r++) {
                int idx = r * 256 + tid;
                vb[r] = *reinterpret_cast<const float4*>(
                    hbBase + (size_t)(idx >> 5) * Hh + hn + ((idx & 31) << 2));
            }
            if (tid < 64) vw = *reinterpret_cast<const float4*>(w2Base + 2 * hn + tid * 4);
        }

        #pragma unroll 8
        for (int c = 0; c < HC; c += 4) {
            float4 xa  = *reinterpret_cast<const float4*>(&sha[li][c]);
            float4 xb0 = *reinterpret_cast<const float4*>(&shb[lj][c]);
            float4 xb1 = *reinterpret_cast<const float4*>(&shb[lj + 16][c]);
            float4 w01 = *reinterpret_cast<const float4*>(&sw2[c]);       // h=c, c+1
            float4 w23 = *reinterpret_cast<const float4*>(&sw2[c + 2]);   // h=c+2, c+3

            float s;
            s = fmaxf(xa.x + xb0.x, 0.f);
            a00 = fmaf(s, w01.x, a00); a01 = fmaf(s, w01.y, a01);
            s = fmaxf(xa.x + xb1.x, 0.f);
            a10 = fmaf(s, w01.x, a10); a11 = fmaf(s, w01.y, a11);
            s = fmaxf(xa.y + xb0.y, 0.f);
            a00 = fmaf(s, w01.z, a00); a01 = fmaf(s, w01.w, a01);
            s = fmaxf(xa.y + xb1.y, 0.f);
            a10 = fmaf(s, w01.z, a10); a11 = fmaf(s, w01.w, a11);
            s = fmaxf(xa.z + xb0.z, 0.f);
            a00 = fmaf(s, w23.x, a00); a01 = fmaf(s, w23.y, a01);
            s = fmaxf(xa.z + xb1.z, 0.f);
            a10 = fmaf(s, w23.x, a10); a11 = fmaf(s, w23.y, a11);
            s = fmaxf(xa.w + xb0.w, 0.f);
            a00 = fmaf(s, w23.z, a00); a01 = fmaf(s, w23.w, a01);
            s = fmaxf(xa.w + xb1.w, 0.f);
            a10 = fmaf(s, w23.z, a10); a11 = fmaf(s, w23.w, a11);
        }
    }

    size_t base = ((size_t)bb * Ss + bi * TI + li) * Ss + bj * TJ + lj;
    g_part[hh][base]      = make_float2(a00, a01);
    g_part[hh][base + 16] = make_float2(a10, a11);
}

// ---------------------------------------------------------------------------
// reduce_kernel: out = part0 + part1 + b2. Full-coverage write (no init
// needed). 128 blocks x 256 thr, one float4 (2 output pairs) per thread.
// ---------------------------------------------------------------------------
__global__ __launch_bounds__(256) void reduce_kernel(
    const float* __restrict__ b2, float4* __restrict__ out)
{
    const int idx = blockIdx.x * 256 + threadIdx.x;
    const float4 p = reinterpret_cast<const float4*>(g_part[0])[idx];
    const float4 q = reinterpret_cast<const float4*>(g_part[1])[idx];
    const float b20 = b2[0], b21 = b2[1];
    out[idx] = make_float4(p.x + q.x + b20, p.y + q.y + b21,
                           p.z + q.z + b20, p.w + q.w + b21);
}

// ---------------------------------------------------------------------------
// launch
// ---------------------------------------------------------------------------
extern "C" void kernel_launch(void* const* d_in, const int* in_sizes, int n_in,
                              void* d_out, int out_size)
{
    // Input mapping by element count:
    // a,b: 393216 ; W1: 1179648 ; b1: 768 ; W2: 1536 ; b2: 2
    const float *a = nullptr, *b = nullptr, *W1 = nullptr, *b1 = nullptr,
                *W2 = nullptr, *b2 = nullptr;
    for (int i = 0; i < n_in; i++) {
        const float* p = (const float*)d_in[i];
        switch (in_sizes[i]) {
            case NA:          if (!a) a = p; else b = p; break;  // a first, then b
            case NW:          W1 = p; break;
            case Hh:          b1 = p; break;
            case Hh * 2:      W2 = p; break;
            case 2:           b2 = p; break;
            default: break;
        }
    }

    cudaFuncSetAttribute(gemm_kernel,
                         cudaFuncAttributeMaxDynamicSharedMemorySize, SM_TOT);

    split_kernel<<<(2 * NA + NW) / 2048, 256>>>(a, b, W1);
    gemm_kernel<<<dim3(MT / GBM, Hh / GBN, 2), 256, SM_TOT>>>(b1);
    pair_kernel<<<dim3(Ss / TI, Ss / TJ, 2 * Bb), 256>>>(W2);
    reduce_kernel<<<(Bb * Ss * Ss) / 512, 256>>>(b2, (float4*)d_out);

    (void)out_size;
}

// round 12
// speedup vs baseline: 1.0068x; 1.0068x over previous
#include <cuda_runtime.h>
#include <cuda_bf16.h>
#include <mma.h>
#include <cstdint>

using namespace nvcuda;

// Problem constants
#define Bb 4
#define Ss 128
#define Dd 768
#define Hh 768
#define MT (Bb * Ss)          // 512 rows per projection GEMM
#define NA (MT * Dd)          // 393216 elements in a (and in b)
#define NW (2 * Dd * Hh)      // 1179648 elements in W1

// ---------------------------------------------------------------------------
// Device scratch (allocation-free rule: __device__ globals)
// ---------------------------------------------------------------------------
__device__ float g_ha[MT * Hh];   // a @ W1[:D] + b1
__device__ float g_hb[MT * Hh];   // b @ W1[D:]

// bf16 split operands, SAME layout as sources
__device__ __align__(16) __nv_bfloat16 g_xa_hi[NA], g_xa_lo[NA];   // [m][d]
__device__ __align__(16) __nv_bfloat16 g_xb_hi[NA], g_xb_lo[NA];   // [m][d]
__device__ __align__(16) __nv_bfloat16 g_w_hi[NW],  g_w_lo[NW];    // [d'][h]

typedef unsigned long long u64;

// packed f32x2 helpers (pair kernel, known-good path)
static __device__ __forceinline__ u64 pk_dup(float x) {
    u64 r; asm("mov.b64 %0, {%1, %1};" : "=l"(r) : "f"(x)); return r;
}
static __device__ __forceinline__ void fma2(u64& d, u64 a, u64 b) {
    asm("fma.rn.f32x2 %0, %1, %2, %0;" : "+l"(d) : "l"(a), "l"(b));
}
static __device__ __forceinline__ void upk(u64 v, float& lo, float& hi) {
    asm("mov.b64 {%0, %1}, %2;" : "=f"(lo), "=f"(hi) : "l"(v));
}

// ---------------------------------------------------------------------------
// split_kernel: fused fp32 -> (hi, lo) bf16 split for a, b, W1.
// 8 elems/thread (2x float4). 960 blocks x 256 thr. (validated in 52.3us run)
// ---------------------------------------------------------------------------
__global__ __launch_bounds__(256) void split_kernel(
    const float* __restrict__ a, const float* __restrict__ b,
    const float* __restrict__ W1)
{
    int i8 = (blockIdx.x * 256 + threadIdx.x) * 8;
    const float* __restrict__ src;
    __nv_bfloat16 *dhi, *dlo;
    int off;
    if (i8 < NA)            { src = a;  dhi = g_xa_hi; dlo = g_xa_lo; off = i8; }
    else if (i8 < 2 * NA)   { src = b;  dhi = g_xb_hi; dlo = g_xb_lo; off = i8 - NA; }
    else                    { src = W1; dhi = g_w_hi;  dlo = g_w_lo;  off = i8 - 2 * NA; }

    float4 v0 = *reinterpret_cast<const float4*>(src + off);
    float4 v1 = *reinterpret_cast<const float4*>(src + off + 4);

    float f[8] = {v0.x, v0.y, v0.z, v0.w, v1.x, v1.y, v1.z, v1.w};
    __nv_bfloat16 h[8], l[8];
    #pragma unroll
    for (int i = 0; i < 8; i++) {
        h[i] = __float2bfloat16(f[i]);
        l[i] = __float2bfloat16(f[i] - __bfloat162float(h[i]));
    }
    *reinterpret_cast<uint4*>(dhi + off) = *reinterpret_cast<uint4*>(h);
    *reinterpret_cast<uint4*>(dlo + off) = *reinterpret_cast<uint4*>(l);
}

// ---------------------------------------------------------------------------
// gemm_kernel: h[z] = X[z] @ W1[z] (+ b1 for z=0), wmma bf16 HMMA.
// 3 split terms (hi*Whi + lo*Whi + hi*Wlo). SINGLE CHANGE UNDER TEST this
// round: TERM-OUTER MMA ordering — 4 independent (i,j) accumulators between
// reuses of any accumulator (was: 3 dependent HMMAs back-to-back per (i,j)).
// BM=128, BN=64, BK=32, 24 k-blocks, 8 warps (4x2), warp tile 32x32.
// grid (4, 12, 2) = 96 CTAs, 256 threads, dynamic smem 59.6KB.
// ---------------------------------------------------------------------------
#define GBM 128
#define GBN 64
#define GBK 32
#define LDA 40
#define LDB 72
#define LDC 68
#define NKB (Dd / GBK)   // 24

#define OFF_AH 0
#define OFF_AL (OFF_AH + 2 * GBM * LDA * 2)
#define OFF_BH (OFF_AL + 2 * GBM * LDA * 2)
#define OFF_BL (OFF_BH + 2 * GBK * LDB * 2)
#define OFF_END (OFF_BL + 2 * GBK * LDB * 2)
#define OFF_BIAS OFF_END
#define SM_TOT (OFF_BIAS + 256)

__global__ __launch_bounds__(256) void gemm_kernel(const float* __restrict__ b1)
{
    extern __shared__ __align__(16) char sm[];
    __nv_bfloat16 (*AsH)[GBM][LDA] = reinterpret_cast<__nv_bfloat16(*)[GBM][LDA]>(sm + OFF_AH);
    __nv_bfloat16 (*AsL)[GBM][LDA] = reinterpret_cast<__nv_bfloat16(*)[GBM][LDA]>(sm + OFF_AL);
    __nv_bfloat16 (*BsH)[GBK][LDB] = reinterpret_cast<__nv_bfloat16(*)[GBK][LDB]>(sm + OFF_BH);
    __nv_bfloat16 (*BsL)[GBK][LDB] = reinterpret_cast<__nv_bfloat16(*)[GBK][LDB]>(sm + OFF_BL);
    float (*Cs)[LDC] = reinterpret_cast<float(*)[LDC]>(sm);
    float* bias = reinterpret_cast<float*>(sm + OFF_BIAS);

    const int tid = threadIdx.x;
    const int wid = tid >> 5;
    const int wm = wid & 3;
    const int wn = wid >> 2;
    const int m_tile = blockIdx.x * GBM;
    const int n_tile = blockIdx.y * GBN;
    const int z = blockIdx.z;

    const __nv_bfloat16* __restrict__ XH = z ? g_xb_hi : g_xa_hi;
    const __nv_bfloat16* __restrict__ XL = z ? g_xb_lo : g_xa_lo;
    const __nv_bfloat16* __restrict__ WH = g_w_hi + (size_t)z * Dd * Hh;
    const __nv_bfloat16* __restrict__ WL = g_w_lo + (size_t)z * Dd * Hh;
    float* __restrict__ Cg = z ? g_hb : g_ha;

    if (tid < GBN)
        bias[tid] = z ? 0.f : b1[n_tile + tid];

    const int ar0 = tid >> 2;
    const int ar1 = (tid + 256) >> 2;
    const int ac  = (tid & 3) * 8;
    const int br = tid >> 3;
    const int bc = (tid & 7) * 8;

    const __nv_bfloat16* XHp0 = XH + (size_t)(m_tile + ar0) * Dd + ac;
    const __nv_bfloat16* XHp1 = XH + (size_t)(m_tile + ar1) * Dd + ac;
    const __nv_bfloat16* XLp0 = XL + (size_t)(m_tile + ar0) * Dd + ac;
    const __nv_bfloat16* XLp1 = XL + (size_t)(m_tile + ar1) * Dd + ac;
    const __nv_bfloat16* WHp  = WH + (size_t)br * Hh + n_tile + bc;
    const __nv_bfloat16* WLp  = WL + (size_t)br * Hh + n_tile + bc;

    {
        *reinterpret_cast<uint4*>(&AsH[0][ar0][ac]) = *reinterpret_cast<const uint4*>(XHp0);
        *reinterpret_cast<uint4*>(&AsH[0][ar1][ac]) = *reinterpret_cast<const uint4*>(XHp1);
        *reinterpret_cast<uint4*>(&AsL[0][ar0][ac]) = *reinterpret_cast<const uint4*>(XLp0);
        *reinterpret_cast<uint4*>(&AsL[0][ar1][ac]) = *reinterpret_cast<const uint4*>(XLp1);
        *reinterpret_cast<uint4*>(&BsH[0][br][bc])  = *reinterpret_cast<const uint4*>(WHp);
        *reinterpret_cast<uint4*>(&BsL[0][br][bc])  = *reinterpret_cast<const uint4*>(WLp);
    }
    __syncthreads();

    wmma::fragment<wmma::accumulator, 16, 16, 16, float> acc[2][2];
    #pragma unroll
    for (int i = 0; i < 2; i++)
        #pragma unroll
        for (int j = 0; j < 2; j++)
            wmma::fill_fragment(acc[i][j], 0.f);

    uint4 pah0, pah1, pal0, pal1, pbh, pbl;
    for (int kb = 0; kb < NKB; kb++) {
        const int cur = kb & 1;
        if (kb + 1 < NKB) {
            const int ko = (kb + 1) * GBK;
            pah0 = *reinterpret_cast<const uint4*>(XHp0 + ko);
            pah1 = *reinterpret_cast<const uint4*>(XHp1 + ko);
            pal0 = *reinterpret_cast<const uint4*>(XLp0 + ko);
            pal1 = *reinterpret_cast<const uint4*>(XLp1 + ko);
            pbh  = *reinterpret_cast<const uint4*>(WHp + (size_t)ko * Hh);
            pbl  = *reinterpret_cast<const uint4*>(WLp + (size_t)ko * Hh);
        }

        #pragma unroll
        for (int ks = 0; ks < GBK; ks += 16) {
            wmma::fragment<wmma::matrix_a, 16, 16, 16, __nv_bfloat16,
                           wmma::row_major> afH[2], afL[2];
            wmma::fragment<wmma::matrix_b, 16, 16, 16, __nv_bfloat16,
                           wmma::row_major> bfH[2], bfL[2];
            #pragma unroll
            for (int i = 0; i < 2; i++) {
                wmma::load_matrix_sync(afH[i], &AsH[cur][wm * 32 + 16 * i][ks], LDA);
                wmma::load_matrix_sync(afL[i], &AsL[cur][wm * 32 + 16 * i][ks], LDA);
            }
            #pragma unroll
            for (int j = 0; j < 2; j++) {
                wmma::load_matrix_sync(bfH[j], &BsH[cur][ks][wn * 32 + 16 * j], LDB);
                wmma::load_matrix_sync(bfL[j], &BsL[cur][ks][wn * 32 + 16 * j], LDB);
            }
            // term-outer: 4 independent accs between reuses of any acc
            #pragma unroll
            for (int i = 0; i < 2; i++)
                #pragma unroll
                for (int j = 0; j < 2; j++)
                    wmma::mma_sync(acc[i][j], afH[i], bfH[j], acc[i][j]);
            #pragma unroll
            for (int i = 0; i < 2; i++)
                #pragma unroll
                for (int j = 0; j < 2; j++)
                    wmma::mma_sync(acc[i][j], afL[i], bfH[j], acc[i][j]);
            #pragma unroll
            for (int i = 0; i < 2; i++)
                #pragma unroll
                for (int j = 0; j < 2; j++)
                    wmma::mma_sync(acc[i][j], afH[i], bfL[j], acc[i][j]);
        }

        if (kb + 1 < NKB) {
            const int nxt = cur ^ 1;
            *reinterpret_cast<uint4*>(&AsH[nxt][ar0][ac]) = pah0;
            *reinterpret_cast<uint4*>(&AsH[nxt][ar1][ac]) = pah1;
            *reinterpret_cast<uint4*>(&AsL[nxt][ar0][ac]) = pal0;
            *reinterpret_cast<uint4*>(&AsL[nxt][ar1][ac]) = pal1;
            *reinterpret_cast<uint4*>(&BsH[nxt][br][bc])  = pbh;
            *reinterpret_cast<uint4*>(&BsL[nxt][br][bc])  = pbl;
        }
        __syncthreads();
    }

    #pragma unroll
    for (int i = 0; i < 2; i++)
        #pragma unroll
        for (int j = 0; j < 2; j++)
            wmma::store_matrix_sync(&Cs[wm * 32 + 16 * i][wn * 32 + 16 * j],
                                    acc[i][j], LDC, wmma::mem_row_major);
    __syncthreads();

    for (int t = tid; t < GBM * (GBN / 4); t += 256) {
        int r  = t >> 4;
        int c4 = (t & 15) * 4;
        float4 v = *reinterpret_cast<const float4*>(&Cs[r][c4]);
        v.x += bias[c4];
        v.y += bias[c4 + 1];
        v.z += bias[c4 + 2];
        v.w += bias[c4 + 3];
        *reinterpret_cast<float4*>(
            Cg + (size_t)(m_tile + r) * Hh + n_tile + c4) = v;
    }
}

// ---------------------------------------------------------------------------
// pair_kernel — EXACT known-good monolithic version (18.66us measured in the
// 51.7us run). Deliberately unchanged for this bisect round.
// out[b,i,j,:] = relu(ha[b,i,:] + hb[b,j,:]) @ W2 + b2
// ---------------------------------------------------------------------------
#define TI 16
#define TJ 32
#define HC 128
#define PP 132

__global__ __launch_bounds__(256) void pair_kernel(
    const float* __restrict__ W2, const float* __restrict__ b2,
    float2* __restrict__ out)
{
    __shared__ float sha[TI][PP];
    __shared__ float shb[TJ][PP];
    __shared__ u64   sw2[HC];      // packed (W2[h,0], W2[h,1])

    const int tid = threadIdx.x;
    const int bi = blockIdx.x, bj = blockIdx.y, bb = blockIdx.z;

    const int li = tid >> 4;   // 0..15 : i within tile
    const int lj = tid & 15;   // j and j+16 within tile

    const float* haBase = g_ha + (size_t)(bb * Ss + bi * TI) * Hh;
    const float* hbBase = g_hb + (size_t)(bb * Ss + bj * TJ) * Hh;

    u64 accA = 0, accB = 0;

    float4 va[2], vb[4], vw;
    {
        #pragma unroll
        for (int r = 0; r < 2; r++) {
            int idx = r * 256 + tid;
            va[r] = *reinterpret_cast<const float4*>(
                haBase + (size_t)(idx >> 5) * Hh + ((idx & 31) << 2));
        }
        #pragma unroll
        for (int r = 0; r < 4; r++) {
            int idx = r * 256 + tid;
            vb[r] = *reinterpret_cast<const float4*>(
                hbBase + (size_t)(idx >> 5) * Hh + ((idx & 31) << 2));
        }
        if (tid < 64) vw = *reinterpret_cast<const float4*>(W2 + tid * 4);
    }

    for (int h0 = 0; h0 < Hh; h0 += HC) {
        __syncthreads();
        #pragma unroll
        for (int r = 0; r < 2; r++) {
            int idx = r * 256 + tid;
            *reinterpret_cast<float4*>(&sha[idx >> 5][(idx & 31) << 2]) = va[r];
        }
        #pragma unroll
        for (int r = 0; r < 4; r++) {
            int idx = r * 256 + tid;
            *reinterpret_cast<float4*>(&shb[idx >> 5][(idx & 31) << 2]) = vb[r];
        }
        if (tid < 64) *reinterpret_cast<float4*>(&sw2[tid * 2]) = vw;
        __syncthreads();

        if (h0 + HC < Hh) {
            int hn = h0 + HC;
            #pragma unroll
            for (int r = 0; r < 2; r++) {
                int idx = r * 256 + tid;
                va[r] = *reinterpret_cast<const float4*>(
                    haBase + (size_t)(idx >> 5) * Hh + hn + ((idx & 31) << 2));
            }
            #pragma unroll
            for (int r = 0; r < 4; r++) {
                int idx = r * 256 + tid;
                vb[r] = *reinterpret_cast<const float4*>(
                    hbBase + (size_t)(idx >> 5) * Hh + hn + ((idx & 31) << 2));
            }
            if (tid < 64) vw = *reinterpret_cast<const float4*>(W2 + 2 * hn + tid * 4);
        }

        #pragma unroll 8
        for (int c = 0; c < HC; c += 4) {
            float4 xa  = *reinterpret_cast<const float4*>(&sha[li][c]);
            float4 xb0 = *reinterpret_cast<const float4*>(&shb[lj][c]);
            float4 xb1 = *reinterpret_cast<const float4*>(&shb[lj + 16][c]);
            u64 w0 = sw2[c], w1 = sw2[c + 1], w2v = sw2[c + 2], w3 = sw2[c + 3];
            float sA, sB;
            sA = fmaxf(xa.x + xb0.x, 0.f); sB = fmaxf(xa.x + xb1.x, 0.f);
            fma2(accA, pk_dup(sA), w0);    fma2(accB, pk_dup(sB), w0);
            sA = fmaxf(xa.y + xb0.y, 0.f); sB = fmaxf(xa.y + xb1.y, 0.f);
            fma2(accA, pk_dup(sA), w1);    fma2(accB, pk_dup(sB), w1);
            sA = fmaxf(xa.z + xb0.z, 0.f); sB = fmaxf(xa.z + xb1.z, 0.f);
            fma2(accA, pk_dup(sA), w2v);   fma2(accB, pk_dup(sB), w2v);
            sA = fmaxf(xa.w + xb0.w, 0.f); sB = fmaxf(xa.w + xb1.w, 0.f);
            fma2(accA, pk_dup(sA), w3);    fma2(accB, pk_dup(sB), w3);
        }
    }

    float aAl, aAh, aBl, aBh;
    upk(accA, aAl, aAh);
    upk(accB, aBl, aBh);
    const float b20 = b2[0], b21 = b2[1];

    size_t base = ((size_t)bb * Ss + bi * TI + li) * Ss + bj * TJ + lj;
    out[base]      = make_float2(aAl + b20, aAh + b21);
    out[base + 16] = make_float2(aBl + b20, aBh + b21);
}

// ---------------------------------------------------------------------------
// launch
// ---------------------------------------------------------------------------
extern "C" void kernel_launch(void* const* d_in, const int* in_sizes, int n_in,
                              void* d_out, int out_size)
{
    // Input mapping by element count:
    // a,b: 393216 ; W1: 1179648 ; b1: 768 ; W2: 1536 ; b2: 2
    const float *a = nullptr, *b = nullptr, *W1 = nullptr, *b1 = nullptr,
                *W2 = nullptr, *b2 = nullptr;
    for (int i = 0; i < n_in; i++) {
        const float* p = (const float*)d_in[i];
        switch (in_sizes[i]) {
            case NA:          if (!a) a = p; else b = p; break;  // a first, then b
            case NW:          W1 = p; break;
            case Hh:          b1 = p; break;
            case Hh * 2:      W2 = p; break;
            case 2:           b2 = p; break;
            default: break;
        }
    }

    cudaFuncSetAttribute(gemm_kernel,
                         cudaFuncAttributeMaxDynamicSharedMemorySize, SM_TOT);

    split_kernel<<<(2 * NA + NW) / 2048, 256>>>(a, b, W1);
    gemm_kernel<<<dim3(MT / GBM, Hh / GBN, 2), 256, SM_TOT>>>(b1);
    pair_kernel<<<dim3(Ss / TI, Ss / TJ, Bb), 256>>>(W2, b2, (float2*)d_out);

    (void)out_size;
}

// round 13
// speedup vs baseline: 1.0583x; 1.0512x over previous
#include <cuda_runtime.h>
#include <cuda_bf16.h>
#include <mma.h>
#include <cstdint>

using namespace nvcuda;

// Problem constants
#define Bb 4
#define Ss 128
#define Dd 768
#define Hh 768
#define MT (Bb * Ss)          // 512 rows per projection GEMM
#define NA (MT * Dd)          // 393216 elements in a (and in b)
#define NW (2 * Dd * Hh)      // 1179648 elements in W1

// ---------------------------------------------------------------------------
// Device scratch (allocation-free rule: __device__ globals)
// ---------------------------------------------------------------------------
__device__ float g_ha[MT * Hh];   // a @ W1[:D] + b1
__device__ float g_hb[MT * Hh];   // b @ W1[D:]

typedef unsigned long long u64;

// packed f32x2 helpers (pair kernel, known-good path)
static __device__ __forceinline__ u64 pk_dup(float x) {
    u64 r; asm("mov.b64 %0, {%1, %1};" : "=l"(r) : "f"(x)); return r;
}
static __device__ __forceinline__ void fma2(u64& d, u64 a, u64 b) {
    asm("fma.rn.f32x2 %0, %1, %2, %0;" : "+l"(d) : "l"(a), "l"(b));
}
static __device__ __forceinline__ void upk(u64 v, float& lo, float& hi) {
    asm("mov.b64 {%0, %1}, %2;" : "=f"(lo), "=f"(hi) : "l"(v));
}

// fp32 -> (hi, lo) bf16 split of 4 values, stored to smem (4 x bf162 stores)
static __device__ __forceinline__ void split_store(
    __nv_bfloat16* dh, __nv_bfloat16* dl, float4 v)
{
    __nv_bfloat16 h0 = __float2bfloat16(v.x), h1 = __float2bfloat16(v.y);
    __nv_bfloat16 h2 = __float2bfloat16(v.z), h3 = __float2bfloat16(v.w);
    __nv_bfloat16 l0 = __float2bfloat16(v.x - __bfloat162float(h0));
    __nv_bfloat16 l1 = __float2bfloat16(v.y - __bfloat162float(h1));
    __nv_bfloat16 l2 = __float2bfloat16(v.z - __bfloat162float(h2));
    __nv_bfloat16 l3 = __float2bfloat16(v.w - __bfloat162float(h3));
    reinterpret_cast<__nv_bfloat162*>(dh)[0] = __nv_bfloat162(h0, h1);
    reinterpret_cast<__nv_bfloat162*>(dh)[1] = __nv_bfloat162(h2, h3);
    reinterpret_cast<__nv_bfloat162*>(dl)[0] = __nv_bfloat162(l0, l1);
    reinterpret_cast<__nv_bfloat162*>(dl)[1] = __nv_bfloat162(l2, l3);
}

// ---------------------------------------------------------------------------
// gemm_kernel: h[z] = X[z] @ W1[z] (+ b1 for z=0), wmma bf16 HMMA.
// NEW THIS ROUND: split kernel FUSED into staging — loads fp32 a/b/W1
// directly, converts to (hi, lo) bf16 in-register while filling smem tiles.
// 3 split terms (hi*Whi + lo*Whi + hi*Wlo), term-outer MMA order.
// BM=128, BN=64, BK=32, 24 k-blocks, 8 warps (4x2), warp tile 32x32.
// grid (4, 12, 2) = 96 CTAs, 256 threads, dynamic smem 59.6KB.
// ---------------------------------------------------------------------------
#define GBM 128
#define GBN 64
#define GBK 32
#define LDA 40
#define LDB 72
#define LDC 68
#define NKB (Dd / GBK)   // 24

#define OFF_AH 0
#define OFF_AL (OFF_AH + 2 * GBM * LDA * 2)
#define OFF_BH (OFF_AL + 2 * GBM * LDA * 2)
#define OFF_BL (OFF_BH + 2 * GBK * LDB * 2)
#define OFF_END (OFF_BL + 2 * GBK * LDB * 2)
#define OFF_BIAS OFF_END
#define SM_TOT (OFF_BIAS + 256)

__global__ __launch_bounds__(256) void gemm_kernel(
    const float* __restrict__ a, const float* __restrict__ b,
    const float* __restrict__ W1, const float* __restrict__ b1)
{
    extern __shared__ __align__(16) char sm[];
    __nv_bfloat16 (*AsH)[GBM][LDA] = reinterpret_cast<__nv_bfloat16(*)[GBM][LDA]>(sm + OFF_AH);
    __nv_bfloat16 (*AsL)[GBM][LDA] = reinterpret_cast<__nv_bfloat16(*)[GBM][LDA]>(sm + OFF_AL);
    __nv_bfloat16 (*BsH)[GBK][LDB] = reinterpret_cast<__nv_bfloat16(*)[GBK][LDB]>(sm + OFF_BH);
    __nv_bfloat16 (*BsL)[GBK][LDB] = reinterpret_cast<__nv_bfloat16(*)[GBK][LDB]>(sm + OFF_BL);
    float (*Cs)[LDC] = reinterpret_cast<float(*)[LDC]>(sm);
    float* bias = reinterpret_cast<float*>(sm + OFF_BIAS);

    const int tid = threadIdx.x;
    const int wid = tid >> 5;
    const int wm = wid & 3;
    const int wn = wid >> 2;
    const int m_tile = blockIdx.x * GBM;
    const int n_tile = blockIdx.y * GBN;
    const int z = blockIdx.z;

    const float* __restrict__ X  = z ? b : a;
    const float* __restrict__ Wg = W1 + (size_t)z * Dd * Hh;
    float* __restrict__ Cg       = z ? g_hb : g_ha;

    if (tid < GBN)
        bias[tid] = z ? 0.f : b1[n_tile + tid];

    // fused staging maps (fp32 float4 granularity)
    // A tile: 128 rows x 32 k = 1024 float4 -> 4 per thread
    int arow[4], ac4[4];
    #pragma unroll
    for (int r = 0; r < 4; r++) {
        int idx = r * 256 + tid;
        arow[r] = idx >> 3;          // 0..127
        ac4[r]  = (idx & 7) * 4;     // 0..28
    }
    // B tile: 32 k-rows x 64 n = 512 float4 -> 2 per thread
    int brow[2], bc4[2];
    #pragma unroll
    for (int r = 0; r < 2; r++) {
        int idx = r * 256 + tid;
        brow[r] = idx >> 4;          // 0..31
        bc4[r]  = (idx & 15) * 4;    // 0..60
    }

    // stage k-block 0 (load fp32, split, store bf16 hi/lo)
    {
        #pragma unroll
        for (int r = 0; r < 4; r++) {
            float4 v = *reinterpret_cast<const float4*>(
                X + (size_t)(m_tile + arow[r]) * Dd + ac4[r]);
            split_store(&AsH[0][arow[r]][ac4[r]], &AsL[0][arow[r]][ac4[r]], v);
        }
        #pragma unroll
        for (int r = 0; r < 2; r++) {
            float4 v = *reinterpret_cast<const float4*>(
                Wg + (size_t)brow[r] * Hh + n_tile + bc4[r]);
            split_store(&BsH[0][brow[r]][bc4[r]], &BsL[0][brow[r]][bc4[r]], v);
        }
    }
    __syncthreads();

    wmma::fragment<wmma::accumulator, 16, 16, 16, float> acc[2][2];
    #pragma unroll
    for (int i = 0; i < 2; i++)
        #pragma unroll
        for (int j = 0; j < 2; j++)
            wmma::fill_fragment(acc[i][j], 0.f);

    float4 pa[4], pb[2];
    for (int kb = 0; kb < NKB; kb++) {
        const int cur = kb & 1;
        if (kb + 1 < NKB) {
            const int ko = (kb + 1) * GBK;
            #pragma unroll
            for (int r = 0; r < 4; r++)
                pa[r] = *reinterpret_cast<const float4*>(
                    X + (size_t)(m_tile + arow[r]) * Dd + ko + ac4[r]);
            #pragma unroll
            for (int r = 0; r < 2; r++)
                pb[r] = *reinterpret_cast<const float4*>(
                    Wg + (size_t)(ko + brow[r]) * Hh + n_tile + bc4[r]);
        }

        #pragma unroll
        for (int ks = 0; ks < GBK; ks += 16) {
            wmma::fragment<wmma::matrix_a, 16, 16, 16, __nv_bfloat16,
                           wmma::row_major> afH[2], afL[2];
            wmma::fragment<wmma::matrix_b, 16, 16, 16, __nv_bfloat16,
                           wmma::row_major> bfH[2], bfL[2];
            #pragma unroll
            for (int i = 0; i < 2; i++) {
                wmma::load_matrix_sync(afH[i], &AsH[cur][wm * 32 + 16 * i][ks], LDA);
                wmma::load_matrix_sync(afL[i], &AsL[cur][wm * 32 + 16 * i][ks], LDA);
            }
            #pragma unroll
            for (int j = 0; j < 2; j++) {
                wmma::load_matrix_sync(bfH[j], &BsH[cur][ks][wn * 32 + 16 * j], LDB);
                wmma::load_matrix_sync(bfL[j], &BsL[cur][ks][wn * 32 + 16 * j], LDB);
            }
            // term-outer: 4 independent accs between reuses of any acc
            #pragma unroll
            for (int i = 0; i < 2; i++)
                #pragma unroll
                for (int j = 0; j < 2; j++)
                    wmma::mma_sync(acc[i][j], afH[i], bfH[j], acc[i][j]);
            #pragma unroll
            for (int i = 0; i < 2; i++)
                #pragma unroll
                for (int j = 0; j < 2; j++)
                    wmma::mma_sync(acc[i][j], afL[i], bfH[j], acc[i][j]);
            #pragma unroll
            for (int i = 0; i < 2; i++)
                #pragma unroll
                for (int j = 0; j < 2; j++)
                    wmma::mma_sync(acc[i][j], afH[i], bfL[j], acc[i][j]);
        }

        if (kb + 1 < NKB) {
            const int nxt = cur ^ 1;
            #pragma unroll
            for (int r = 0; r < 4; r++)
                split_store(&AsH[nxt][arow[r]][ac4[r]],
                            &AsL[nxt][arow[r]][ac4[r]], pa[r]);
            #pragma unroll
            for (int r = 0; r < 2; r++)
                split_store(&BsH[nxt][brow[r]][bc4[r]],
                            &BsL[nxt][brow[r]][bc4[r]], pb[r]);
        }
        __syncthreads();
    }

    // epilogue: stage C through smem (aliases tiles; safe after final sync)
    #pragma unroll
    for (int i = 0; i < 2; i++)
        #pragma unroll
        for (int j = 0; j < 2; j++)
            wmma::store_matrix_sync(&Cs[wm * 32 + 16 * i][wn * 32 + 16 * j],
                                    acc[i][j], LDC, wmma::mem_row_major);
    __syncthreads();

    for (int t = tid; t < GBM * (GBN / 4); t += 256) {
        int r  = t >> 4;
        int c4 = (t & 15) * 4;
        float4 v = *reinterpret_cast<const float4*>(&Cs[r][c4]);
        v.x += bias[c4];
        v.y += bias[c4 + 1];
        v.z += bias[c4 + 2];
        v.w += bias[c4 + 3];
        *reinterpret_cast<float4*>(
            Cg + (size_t)(m_tile + r) * Hh + n_tile + c4) = v;
    }
}

// ---------------------------------------------------------------------------
// pair_kernel — EXACT known-good monolithic version (18.66us measured):
// out[b,i,j,:] = relu(ha[b,i,:] + hb[b,j,:]) @ W2 + b2
// ---------------------------------------------------------------------------
#define TI 16
#define TJ 32
#define HC 128
#define PP 132

__global__ __launch_bounds__(256) void pair_kernel(
    const float* __restrict__ W2, const float* __restrict__ b2,
    float2* __restrict__ out)
{
    __shared__ float sha[TI][PP];
    __shared__ float shb[TJ][PP];
    __shared__ u64   sw2[HC];      // packed (W2[h,0], W2[h,1])

    const int tid = threadIdx.x;
    const int bi = blockIdx.x, bj = blockIdx.y, bb = blockIdx.z;

    const int li = tid >> 4;   // 0..15 : i within tile
    const int lj = tid & 15;   // j and j+16 within tile

    const float* haBase = g_ha + (size_t)(bb * Ss + bi * TI) * Hh;
    const float* hbBase = g_hb + (size_t)(bb * Ss + bj * TJ) * Hh;

    u64 accA = 0, accB = 0;

    float4 va[2], vb[4], vw;
    {
        #pragma unroll
        for (int r = 0; r < 2; r++) {
            int idx = r * 256 + tid;
            va[r] = *reinterpret_cast<const float4*>(
                haBase + (size_t)(idx >> 5) * Hh + ((idx & 31) << 2));
        }
        #pragma unroll
        for (int r = 0; r < 4; r++) {
            int idx = r * 256 + tid;
            vb[r] = *reinterpret_cast<const float4*>(
                hbBase + (size_t)(idx >> 5) * Hh + ((idx & 31) << 2));
        }
        if (tid < 64) vw = *reinterpret_cast<const float4*>(W2 + tid * 4);
    }

    for (int h0 = 0; h0 < Hh; h0 += HC) {
        __syncthreads();
        #pragma unroll
        for (int r = 0; r < 2; r++) {
            int idx = r * 256 + tid;
            *reinterpret_cast<float4*>(&sha[idx >> 5][(idx & 31) << 2]) = va[r];
        }
        #pragma unroll
        for (int r = 0; r < 4; r++) {
            int idx = r * 256 + tid;
            *reinterpret_cast<float4*>(&shb[idx >> 5][(idx & 31) << 2]) = vb[r];
        }
        if (tid < 64) *reinterpret_cast<float4*>(&sw2[tid * 2]) = vw;
        __syncthreads();

        if (h0 + HC < Hh) {
            int hn = h0 + HC;
            #pragma unroll
            for (int r = 0; r < 2; r++) {
                int idx = r * 256 + tid;
                va[r] = *reinterpret_cast<const float4*>(
                    haBase + (size_t)(idx >> 5) * Hh + hn + ((idx & 31) << 2));
            }
            #pragma unroll
            for (int r = 0; r < 4; r++) {
                int idx = r * 256 + tid;
                vb[r] = *reinterpret_cast<const float4*>(
                    hbBase + (size_t)(idx >> 5) * Hh + hn + ((idx & 31) << 2));
            }
            if (tid < 64) vw = *reinterpret_cast<const float4*>(W2 + 2 * hn + tid * 4);
        }

        #pragma unroll 8
        for (int c = 0; c < HC; c += 4) {
            float4 xa  = *reinterpret_cast<const float4*>(&sha[li][c]);
            float4 xb0 = *reinterpret_cast<const float4*>(&shb[lj][c]);
            float4 xb1 = *reinterpret_cast<const float4*>(&shb[lj + 16][c]);
            u64 w0 = sw2[c], w1 = sw2[c + 1], w2v = sw2[c + 2], w3 = sw2[c + 3];
            float sA, sB;
            sA = fmaxf(xa.x + xb0.x, 0.f); sB = fmaxf(xa.x + xb1.x, 0.f);
            fma2(accA, pk_dup(sA), w0);    fma2(accB, pk_dup(sB), w0);
            sA = fmaxf(xa.y + xb0.y, 0.f); sB = fmaxf(xa.y + xb1.y, 0.f);
            fma2(accA, pk_dup(sA), w1);    fma2(accB, pk_dup(sB), w1);
            sA = fmaxf(xa.z + xb0.z, 0.f); sB = fmaxf(xa.z + xb1.z, 0.f);
            fma2(accA, pk_dup(sA), w2v);   fma2(accB, pk_dup(sB), w2v);
            sA = fmaxf(xa.w + xb0.w, 0.f); sB = fmaxf(xa.w + xb1.w, 0.f);
            fma2(accA, pk_dup(sA), w3);    fma2(accB, pk_dup(sB), w3);
        }
    }

    float aAl, aAh, aBl, aBh;
    upk(accA, aAl, aAh);
    upk(accB, aBl, aBh);
    const float b20 = b2[0], b21 = b2[1];

    size_t base = ((size_t)bb * Ss + bi * TI + li) * Ss + bj * TJ + lj;
    out[base]      = make_float2(aAl + b20, aAh + b21);
    out[base + 16] = make_float2(aBl + b20, aBh + b21);
}

// ---------------------------------------------------------------------------
// launch
// ---------------------------------------------------------------------------
extern "C" void kernel_launch(void* const* d_in, const int* in_sizes, int n_in,
                              void* d_out, int out_size)
{
    // Input mapping by element count:
    // a,b: 393216 ; W1: 1179648 ; b1: 768 ; W2: 1536 ; b2: 2
    const float *a = nullptr, *b = nullptr, *W1 = nullptr, *b1 = nullptr,
                *W2 = nullptr, *b2 = nullptr;
    for (int i = 0; i < n_in; i++) {
        const float* p = (const float*)d_in[i];
        switch (in_sizes[i]) {
            case NA:          if (!a) a = p; else b = p; break;  // a first, then b
            case NW:          W1 = p; break;
            case Hh:          b1 = p; break;
            case Hh * 2:      W2 = p; break;
            case 2:           b2 = p; break;
            default: break;
        }
    }

    cudaFuncSetAttribute(gemm_kernel,
                         cudaFuncAttributeMaxDynamicSharedMemorySize, SM_TOT);

    gemm_kernel<<<dim3(MT / GBM, Hh / GBN, 2), 256, SM_TOT>>>(a, b, W1, b1);
    pair_kernel<<<dim3(Ss / TI, Ss / TJ, Bb), 256>>>(W2, b2, (float2*)d_out);

    (void)out_size;
}

// round 15
// speedup vs baseline: 1.0729x; 1.0138x over previous
#include <cuda_runtime.h>
#include <cuda_bf16.h>
#include <mma.h>
#include <cstdint>

using namespace nvcuda;

// Problem constants
#define Bb 4
#define Ss 128
#define Dd 768
#define Hh 768
#define MT (Bb * Ss)          // 512 rows per projection GEMM
#define NA (MT * Dd)          // 393216 elements in a (and in b)
#define NW (2 * Dd * Hh)      // 1179648 elements in W1

// ---------------------------------------------------------------------------
// Device scratch (allocation-free rule: __device__ globals)
// ---------------------------------------------------------------------------
__device__ float g_ha[MT * Hh];   // a @ W1[:D] + b1
__device__ float g_hb[MT * Hh];   // b @ W1[D:]
__device__ __align__(16) float2 g_part[4][Bb * Ss * Ss];   // pair partials

// fp32 -> (hi, lo) bf16 split of 4 values, stored to smem
static __device__ __forceinline__ void split_store(
    __nv_bfloat16* dh, __nv_bfloat16* dl, float4 v)
{
    __nv_bfloat16 h0 = __float2bfloat16(v.x), h1 = __float2bfloat16(v.y);
    __nv_bfloat16 h2 = __float2bfloat16(v.z), h3 = __float2bfloat16(v.w);
    __nv_bfloat16 l0 = __float2bfloat16(v.x - __bfloat162float(h0));
    __nv_bfloat16 l1 = __float2bfloat16(v.y - __bfloat162float(h1));
    __nv_bfloat16 l2 = __float2bfloat16(v.z - __bfloat162float(h2));
    __nv_bfloat16 l3 = __float2bfloat16(v.w - __bfloat162float(h3));
    reinterpret_cast<__nv_bfloat162*>(dh)[0] = __nv_bfloat162(h0, h1);
    reinterpret_cast<__nv_bfloat162*>(dh)[1] = __nv_bfloat162(h2, h3);
    reinterpret_cast<__nv_bfloat162*>(dl)[0] = __nv_bfloat162(l0, l1);
    reinterpret_cast<__nv_bfloat162*>(dl)[1] = __nv_bfloat162(l2, l3);
}

// ---------------------------------------------------------------------------
// gemm_kernel: h[z] = X[z] @ W1[z] (+ b1 for z=0), wmma bf16 HMMA, fused
// fp32->bf16 hi/lo split staging. NEW: BM=64 x BN=96 -> grid (8,8,2) = 128
// CTAs (was 96) — spreads the fixed HMMA budget over more SMs.
// 8 warps as 4M x 2N, warp tile 16x48 (1 A-frag, 3 B-frags, 9 mma/ks).
// ---------------------------------------------------------------------------
#define GBM 64
#define GBN 96
#define GBK 32
#define LDA 40    // 32 k + 8 pad (bf16)
#define LDB 104   // 96 n + 8 pad (bf16)
#define LDC 100   // fp32 epilogue pitch
#define NKB (Dd / GBK)   // 24

#define OFF_AH 0
#define OFF_AL (OFF_AH + 2 * GBM * LDA * 2)   // 10240
#define OFF_BH (OFF_AL + 2 * GBM * LDA * 2)   // 20480
#define OFF_BL (OFF_BH + 2 * GBK * LDB * 2)   // 33792
#define OFF_END (OFF_BL + 2 * GBK * LDB * 2)  // 47104
#define OFF_BIAS OFF_END
#define SM_TOT (OFF_BIAS + 512)               // 47616 (Cs aliases [0, 25600))

__global__ __launch_bounds__(256) void gemm_kernel(
    const float* __restrict__ a, const float* __restrict__ b,
    const float* __restrict__ W1, const float* __restrict__ b1)
{
    extern __shared__ __align__(16) char sm[];
    __nv_bfloat16 (*AsH)[GBM][LDA] = reinterpret_cast<__nv_bfloat16(*)[GBM][LDA]>(sm + OFF_AH);
    __nv_bfloat16 (*AsL)[GBM][LDA] = reinterpret_cast<__nv_bfloat16(*)[GBM][LDA]>(sm + OFF_AL);
    __nv_bfloat16 (*BsH)[GBK][LDB] = reinterpret_cast<__nv_bfloat16(*)[GBK][LDB]>(sm + OFF_BH);
    __nv_bfloat16 (*BsL)[GBK][LDB] = reinterpret_cast<__nv_bfloat16(*)[GBK][LDB]>(sm + OFF_BL);
    float (*Cs)[LDC] = reinterpret_cast<float(*)[LDC]>(sm);
    float* bias = reinterpret_cast<float*>(sm + OFF_BIAS);

    const int tid = threadIdx.x;
    const int wid = tid >> 5;
    const int wm = wid >> 1;          // 0..3 : 16-row M slice
    const int wn = wid & 1;           // 0..1 : 48-col N slice
    const int m_tile = blockIdx.x * GBM;
    const int n_tile = blockIdx.y * GBN;
    const int z = blockIdx.z;

    const float* __restrict__ X  = z ? b : a;
    const float* __restrict__ Wg = W1 + (size_t)z * Dd * Hh;
    float* __restrict__ Cg       = z ? g_hb : g_ha;

    if (tid < GBN)
        bias[tid] = z ? 0.f : b1[n_tile + tid];

    // staging maps (fp32 float4 granularity)
    // A tile: 64 rows x 32 k = 512 float4 -> 2 per thread
    int arow[2], ac4[2];
    #pragma unroll
    for (int r = 0; r < 2; r++) {
        int idx = r * 256 + tid;
        arow[r] = idx >> 3;          // 0..63
        ac4[r]  = (idx & 7) * 4;     // 0..28
    }
    // B tile: 32 k-rows x 96 n = 768 float4 -> 3 per thread
    int brow[3], bc4[3];
    #pragma unroll
    for (int r = 0; r < 3; r++) {
        int idx = r * 256 + tid;
        brow[r] = idx / 24;          // 0..31
        bc4[r]  = (idx % 24) * 4;    // 0..92
    }

    // stage k-block 0
    {
        #pragma unroll
        for (int r = 0; r < 2; r++) {
            float4 v = *reinterpret_cast<const float4*>(
                X + (size_t)(m_tile + arow[r]) * Dd + ac4[r]);
            split_store(&AsH[0][arow[r]][ac4[r]], &AsL[0][arow[r]][ac4[r]], v);
        }
        #pragma unroll
        for (int r = 0; r < 3; r++) {
            float4 v = *reinterpret_cast<const float4*>(
                Wg + (size_t)brow[r] * Hh + n_tile + bc4[r]);
            split_store(&BsH[0][brow[r]][bc4[r]], &BsL[0][brow[r]][bc4[r]], v);
        }
    }
    __syncthreads();

    wmma::fragment<wmma::accumulator, 16, 16, 16, float> acc[3];
    #pragma unroll
    for (int j = 0; j < 3; j++)
        wmma::fill_fragment(acc[j], 0.f);

    float4 pa[2], pb[3];
    for (int kb = 0; kb < NKB; kb++) {
        const int cur = kb & 1;
        if (kb + 1 < NKB) {
            const int ko = (kb + 1) * GBK;
            #pragma unroll
            for (int r = 0; r < 2; r++)
                pa[r] = *reinterpret_cast<const float4*>(
                    X + (size_t)(m_tile + arow[r]) * Dd + ko + ac4[r]);
            #pragma unroll
            for (int r = 0; r < 3; r++)
                pb[r] = *reinterpret_cast<const float4*>(
                    Wg + (size_t)(ko + brow[r]) * Hh + n_tile + bc4[r]);
        }

        #pragma unroll
        for (int ks = 0; ks < GBK; ks += 16) {
            wmma::fragment<wmma::matrix_a, 16, 16, 16, __nv_bfloat16,
                           wmma::row_major> afH, afL;
            wmma::fragment<wmma::matrix_b, 16, 16, 16, __nv_bfloat16,
                           wmma::row_major> bfH[3], bfL[3];
            wmma::load_matrix_sync(afH, &AsH[cur][wm * 16][ks], LDA);
            wmma::load_matrix_sync(afL, &AsL[cur][wm * 16][ks], LDA);
            #pragma unroll
            for (int j = 0; j < 3; j++) {
                wmma::load_matrix_sync(bfH[j], &BsH[cur][ks][wn * 48 + 16 * j], LDB);
                wmma::load_matrix_sync(bfL[j], &BsL[cur][ks][wn * 48 + 16 * j], LDB);
            }
            // term-outer: 3 independent accs between reuses
            #pragma unroll
            for (int j = 0; j < 3; j++)
                wmma::mma_sync(acc[j], afH, bfH[j], acc[j]);
            #pragma unroll
            for (int j = 0; j < 3; j++)
                wmma::mma_sync(acc[j], afL, bfH[j], acc[j]);
            #pragma unroll
            for (int j = 0; j < 3; j++)
                wmma::mma_sync(acc[j], afH, bfL[j], acc[j]);
        }

        if (kb + 1 < NKB) {
            const int nxt = cur ^ 1;
            #pragma unroll
            for (int r = 0; r < 2; r++)
                split_store(&AsH[nxt][arow[r]][ac4[r]],
                            &AsL[nxt][arow[r]][ac4[r]], pa[r]);
            #pragma unroll
            for (int r = 0; r < 3; r++)
                split_store(&BsH[nxt][brow[r]][bc4[r]],
                            &BsL[nxt][brow[r]][bc4[r]], pb[r]);
        }
        __syncthreads();
    }

    // epilogue: stage C through smem (aliases tiles; safe after final sync)
    #pragma unroll
    for (int j = 0; j < 3; j++)
        wmma::store_matrix_sync(&Cs[wm * 16][wn * 48 + 16 * j],
                                acc[j], LDC, wmma::mem_row_major);
    __syncthreads();

    // biased coalesced write: 64 rows x 24 float4 = 1536 f4 over 256 thr
    for (int t = tid; t < GBM * (GBN / 4); t += 256) {
        int r  = t / 24;
        int c4 = (t % 24) * 4;
        float4 v = *reinterpret_cast<const float4*>(&Cs[r][c4]);
        v.x += bias[c4];
        v.y += bias[c4 + 1];
        v.z += bias[c4 + 2];
        v.w += bias[c4 + 3];
        *reinterpret_cast<float4*>(
            Cg + (size_t)(m_tile + r) * Hh + n_tile + c4) = v;
    }
}

// ---------------------------------------------------------------------------
// pair_kernel: partial[hh][b,i,j,:] = relu(ha+hb)[:, hh*192:(hh+1)*192] @ W2
// 4-way h-split across blockIdx.z (grid (8,4,16) = 512 CTAs, 4096 warps).
// Same proven-safe 256-thread static-smem pattern as the PASSING R9 variant.
// Single h-chunk of 192 in smem (no streaming loop). Scalar-FFMA inner loop.
// ---------------------------------------------------------------------------
#define PTI 16
#define PTJ 32
#define HQ 192
#define PPP 196   // padded pitch (f32)

__global__ __launch_bounds__(256) void pair_kernel(const float* __restrict__ W2)
{
    __shared__ float sha[PTI][PPP];
    __shared__ float shb[PTJ][PPP];
    __shared__ float2 sw2[HQ];

    const int tid = threadIdx.x;
    const int bi = blockIdx.x, bj = blockIdx.y;
    const int bb = blockIdx.z >> 2;
    const int hh = blockIdx.z & 3;
    const int hbase = hh * HQ;

    const int li = tid >> 4;   // 0..15 : i within tile
    const int lj = tid & 15;   // j and j+16 within tile

    const float* haBase = g_ha + (size_t)(bb * Ss + bi * PTI) * Hh + hbase;
    const float* hbBase = g_hb + (size_t)(bb * Ss + bj * PTJ) * Hh + hbase;
    const float* w2Base = W2 + 2 * hbase;

    // stage: sha 16x192 (768 f4 -> 3/thread), shb 32x192 (1536 f4 -> 6/thread)
    #pragma unroll
    for (int r = 0; r < 3; r++) {
        int idx = r * 256 + tid;
        int row = idx / 48, c4 = (idx % 48) * 4;
        *reinterpret_cast<float4*>(&sha[row][c4]) =
            *reinterpret_cast<const float4*>(haBase + (size_t)row * Hh + c4);
    }
    #pragma unroll
    for (int r = 0; r < 6; r++) {
        int idx = r * 256 + tid;
        int row = idx / 48, c4 = (idx % 48) * 4;
        *reinterpret_cast<float4*>(&shb[row][c4]) =
            *reinterpret_cast<const float4*>(hbBase + (size_t)row * Hh + c4);
    }
    if (tid < 96)
        reinterpret_cast<float4*>(sw2)[tid] =
            reinterpret_cast<const float4*>(w2Base)[tid];
    __syncthreads();

    float a00 = 0.f, a01 = 0.f, a10 = 0.f, a11 = 0.f;   // acc[j][o]

    #pragma unroll 8
    for (int c = 0; c < HQ; c += 4) {
        float4 xa  = *reinterpret_cast<const float4*>(&sha[li][c]);
        float4 xb0 = *reinterpret_cast<const float4*>(&shb[lj][c]);
        float4 xb1 = *reinterpret_cast<const float4*>(&shb[lj + 16][c]);
        float4 w01 = *reinterpret_cast<const float4*>(&sw2[c]);       // h=c, c+1
        float4 w23 = *reinterpret_cast<const float4*>(&sw2[c + 2]);   // h=c+2, c+3

        float s;
        s = fmaxf(xa.x + xb0.x, 0.f);
        a00 = fmaf(s, w01.x, a00); a01 = fmaf(s, w01.y, a01);
        s = fmaxf(xa.x + xb1.x, 0.f);
        a10 = fmaf(s, w01.x, a10); a11 = fmaf(s, w01.y, a11);
        s = fmaxf(xa.y + xb0.y, 0.f);
        a00 = fmaf(s, w01.z, a00); a01 = fmaf(s, w01.w, a01);
        s = fmaxf(xa.y + xb1.y, 0.f);
        a10 = fmaf(s, w01.z, a10); a11 = fmaf(s, w01.w, a11);
        s = fmaxf(xa.z + xb0.z, 0.f);
        a00 = fmaf(s, w23.x, a00); a01 = fmaf(s, w23.y, a01);
        s = fmaxf(xa.z + xb1.z, 0.f);
        a10 = fmaf(s, w23.x, a10); a11 = fmaf(s, w23.y, a11);
        s = fmaxf(xa.w + xb0.w, 0.f);
        a00 = fmaf(s, w23.z, a00); a01 = fmaf(s, w23.w, a01);
        s = fmaxf(xa.w + xb1.w, 0.f);
        a10 = fmaf(s, w23.z, a10); a11 = fmaf(s, w23.w, a11);
    }

    size_t base = ((size_t)bb * Ss + bi * PTI + li) * Ss + bj * PTJ + lj;
    g_part[hh][base]      = make_float2(a00, a01);
    g_part[hh][base + 16] = make_float2(a10, a11);
}

// ---------------------------------------------------------------------------
// reduce_kernel: out = part0+part1+part2+part3 + b2. 64 CTAs x 256 thr,
// 2 float4 per thread, 8 independent loads in flight (MLP 8).
// ---------------------------------------------------------------------------
__global__ __launch_bounds__(256) void reduce_kernel(
    const float* __restrict__ b2, float4* __restrict__ out)
{
    const int i0 = blockIdx.x * 256 + threadIdx.x;        // 0..16383
    const int i1 = i0 + 16384;
    const float4* P0 = reinterpret_cast<const float4*>(g_part[0]);
    const float4* P1 = reinterpret_cast<const float4*>(g_part[1]);
    const float4* P2 = reinterpret_cast<const float4*>(g_part[2]);
    const float4* P3 = reinterpret_cast<const float4*>(g_part[3]);

    float4 a0 = P0[i0], a1 = P1[i0], a2 = P2[i0], a3 = P3[i0];
    float4 c0 = P0[i1], c1 = P1[i1], c2 = P2[i1], c3 = P3[i1];
    const float b20 = b2[0], b21 = b2[1];

    out[i0] = make_float4(a0.x + a1.x + a2.x + a3.x + b20,
                          a0.y + a1.y + a2.y + a3.y + b21,
                          a0.z + a1.z + a2.z + a3.z + b20,
                          a0.w + a1.w + a2.w + a3.w + b21);
    out[i1] = make_float4(c0.x + c1.x + c2.x + c3.x + b20,
                          c0.y + c1.y + c2.y + c3.y + b21,
                          c0.z + c1.z + c2.z + c3.z + b20,
                          c0.w + c1.w + c2.w + c3.w + b21);
}

// ---------------------------------------------------------------------------
// launch
// ---------------------------------------------------------------------------
extern "C" void kernel_launch(void* const* d_in, const int* in_sizes, int n_in,
                              void* d_out, int out_size)
{
    // Input mapping by element count:
    // a,b: 393216 ; W1: 1179648 ; b1: 768 ; W2: 1536 ; b2: 2
    const float *a = nullptr, *b = nullptr, *W1 = nullptr, *b1 = nullptr,
                *W2 = nullptr, *b2 = nullptr;
    for (int i = 0; i < n_in; i++) {
        const float* p = (const float*)d_in[i];
        switch (in_sizes[i]) {
            case NA:          if (!a) a = p; else b = p; break;  // a first, then b
            case NW:          W1 = p; break;
            case Hh:          b1 = p; break;
            case Hh * 2:      W2 = p; break;
            case 2:           b2 = p; break;
            default: break;
        }
    }

    cudaFuncSetAttribute(gemm_kernel,
                         cudaFuncAttributeMaxDynamicSharedMemorySize, SM_TOT);

    gemm_kernel<<<dim3(MT / GBM, Hh / GBN, 2), 256, SM_TOT>>>(a, b, W1, b1);
    pair_kernel<<<dim3(Ss / PTI, Ss / PTJ, 4 * Bb), 256>>>(W2);
    reduce_kernel<<<64, 256>>>(b2, (float4*)d_out);

    (void)out_size;
}